// round 1
// baseline (speedup 1.0000x reference)
#include <cuda_runtime.h>
#include <cstdint>
#include <math.h>

// ---------------------------------------------------------------------------
// SimpleConvRNN fused kernel for GB300 (sm_103a)
// Pipeline: mem gather + FTL(4x4) -> concat -> [128x128 GEMM + bias + relu] x2
//           -> [64x128 GEMM + bias] -> out (channels 64..127)
// Strategy: persistent CTAs (1/SM, 196KB smem holding all transposed weights),
// per-tile x staging in smem, packed fp32x2 FMA inner loops.
// ---------------------------------------------------------------------------

namespace {
constexpr int kB       = 32;
constexpr int kH       = 64;
constexpr int kW       = 96;
constexpr int kHW      = kH * kW;          // 6144
constexpr int kNC      = 128;
constexpr int kTILE    = 64;               // pixels per tile
constexpr int kTHREADS = 256;
constexpr int kXP      = 68;               // xs pitch (floats): 272B, 16B-aligned rows
constexpr int kWP      = 129;              // transposed-weight pitch (odd: conflict-free)
constexpr int kWP2     = 65;               // layer-2 weight pitch (64 outputs)
constexpr int kTilesPerB = kHW / kTILE;    // 96
constexpr int kNTiles  = kB * kTilesPerB;  // 3072

constexpr int W0_OFF = 0;
constexpr int W1_OFF = W0_OFF + 128 * kWP;
constexpr int W2_OFF = W1_OFF + 128 * kWP;
constexpr int XS_OFF = W2_OFF + 128 * kWP2;
constexpr int SB_OFF = XS_OFF + 128 * kXP;
constexpr int XF_OFF = SB_OFF + 384;
constexpr int SMEM_FLOATS = XF_OFF + 16;
constexpr size_t SMEM_BYTES = (size_t)SMEM_FLOATS * sizeof(float);  // ~201.8 KB
}

typedef unsigned long long u64;

__device__ __forceinline__ u64 pack2(float a, float b) {
    u64 r;
    asm("mov.b64 %0, {%1, %2};" : "=l"(r) : "f"(a), "f"(b));
    return r;
}
__device__ __forceinline__ void fma2(u64& d, u64 a, u64 b) {
    asm("fma.rn.f32x2 %0, %1, %2, %0;" : "+l"(d) : "l"(a), "l"(b));
}
__device__ __forceinline__ float2 unpack2(u64 v) {
    float2 f;
    asm("mov.b64 {%0, %1}, %2;" : "=f"(f.x), "=f"(f.y) : "l"(v));
    return f;
}

// Per-batch precomputed state (written by prep kernel)
__device__ float g_xf[kB * 16];
__device__ int   g_use[kB];
__device__ int   g_midx[kB];

// ---------------------------------------------------------------------------
// Prep kernel: decode use_memory (dtype auto-detect), gather extrinsics,
// 4x4 inverse (Gauss-Jordan, partial pivot), xf = cur @ inv(prev).
// ---------------------------------------------------------------------------
__global__ void prep_kernel(const float* __restrict__ prev_ext,
                            const float* __restrict__ cur_ext,
                            const int*   __restrict__ memory_idx,
                            const unsigned char* __restrict__ use_raw) {
    int b = threadIdx.x;
    if (b >= kB) return;

    // --- detect use_memory layout: int32 / float32 / uint8 (first 32 bytes) ---
    const unsigned int* w32 = (const unsigned int*)use_raw;
    bool int_layout = true, float_layout = true;
    #pragma unroll
    for (int i = 0; i < 8; i++) {
        unsigned int v = w32[i];
        if (v != 0u && v != 1u)          int_layout = false;
        if (v != 0u && v != 0x3f800000u) float_layout = false;
    }
    int use;
    if (int_layout || float_layout) use = (w32[b] != 0u) ? 1 : 0;
    else                            use = use_raw[b] ? 1 : 0;
    g_use[b] = use;

    int m = memory_idx[b];
    g_midx[b] = m;

    // --- safe_prev = use ? prev_ext[m] : I ; invert via Gauss-Jordan ---
    float A[4][8];
    #pragma unroll
    for (int r = 0; r < 4; r++) {
        #pragma unroll
        for (int c = 0; c < 4; c++) {
            A[r][c]     = use ? prev_ext[(size_t)m * 16 + r * 4 + c]
                              : (r == c ? 1.f : 0.f);
            A[r][c + 4] = (r == c) ? 1.f : 0.f;
        }
    }
    for (int col = 0; col < 4; col++) {
        int piv = col;
        float best = fabsf(A[col][col]);
        for (int r = col + 1; r < 4; r++) {
            float v = fabsf(A[r][col]);
            if (v > best) { best = v; piv = r; }
        }
        if (piv != col) {
            for (int j = 0; j < 8; j++) {
                float t = A[col][j]; A[col][j] = A[piv][j]; A[piv][j] = t;
            }
        }
        float inv = 1.f / A[col][col];
        for (int j = 0; j < 8; j++) A[col][j] *= inv;
        for (int r = 0; r < 4; r++) {
            if (r == col) continue;
            float f = A[r][col];
            for (int j = 0; j < 8; j++) A[r][j] -= f * A[col][j];
        }
    }
    // xf = cur_ext[b] @ inv(safe_prev)
    #pragma unroll
    for (int i = 0; i < 4; i++) {
        #pragma unroll
        for (int j = 0; j < 4; j++) {
            float s = 0.f;
            #pragma unroll
            for (int k = 0; k < 4; k++)
                s += cur_ext[(size_t)b * 16 + i * 4 + k] * A[k][4 + j];
            g_xf[b * 16 + i * 4 + j] = s;
        }
    }
}

// ---------------------------------------------------------------------------
// Main fused kernel: persistent CTAs, loops over pixel tiles.
// ---------------------------------------------------------------------------
__global__ void __launch_bounds__(kTHREADS, 1)
fused_kernel(const float* __restrict__ img,
             const float* __restrict__ mem,
             const float* __restrict__ Ws,
             const float* __restrict__ bs,
             float* __restrict__ out) {
    extern __shared__ float sm[];
    float* Wt0 = sm + W0_OFF;   // [k][o], pitch 129
    float* Wt1 = sm + W1_OFF;
    float* Wt2 = sm + W2_OFF;   // [k][o-64], pitch 65
    float* xs  = sm + XS_OFF;   // [ch][px], pitch 68
    float* sb  = sm + SB_OFF;   // 3*128 biases
    float* sxf = sm + XF_OFF;   // 16

    const int tid = threadIdx.x;

    // ---- one-time weight staging (coalesced gmem reads, transposed smem) ----
    for (int i = tid; i < 128 * 128; i += kTHREADS) {
        int o = i >> 7, k = i & 127;
        Wt0[k * kWP + o] = Ws[i];
        Wt1[k * kWP + o] = Ws[16384 + i];
    }
    for (int i = tid; i < 64 * 128; i += kTHREADS) {
        int o = i >> 7, k = i & 127;                    // o: 0..63 -> out ch 64+o
        Wt2[k * kWP2 + o] = Ws[2 * 16384 + (64 + o) * 128 + k];
    }
    for (int i = tid; i < 384; i += kTHREADS) sb[i] = bs[i];
    __syncthreads();

    const int c    = tid & 127;     // channel (layers 0,1)
    const int half = tid >> 7;      // pixel half (layers 0,1)
    const int c2   = tid & 63;      // out channel - 64 (layer 2)
    const int quad = tid >> 6;      // pixel quarter (layer 2)

    for (int t = blockIdx.x; t < kNTiles; t += gridDim.x) {
        const int b  = t / kTilesPerB;
        const int p0 = (t % kTilesPerB) * kTILE;

        if (tid < 16) sxf[tid] = g_xf[b * 16 + tid];
        const int useb = g_use[b];
        const int m    = g_midx[b];
        __syncthreads();   // protects xs (prev tile reads done) + sxf visible

        // ---- stage x tile: channels 64..127 = img ----
        for (int i = tid; i < 64 * 16; i += kTHREADS) {
            int ch = i >> 4, p4 = (i & 15) * 4;
            float4 v = *(const float4*)(img + (size_t)(b * 64 + ch) * kHW + p0 + p4);
            *(float4*)(xs + (64 + ch) * kXP + p4) = v;
        }
        // ---- channels 0..63 = mem (FTL on 0..31) or zeros ----
        if (useb) {
            for (int i = tid; i < 32 * 16; i += kTHREADS) {
                int ch = i >> 4, p4 = (i & 15) * 4;
                float4 v = *(const float4*)(mem + (size_t)(m * 64 + 32 + ch) * kHW + p0 + p4);
                *(float4*)(xs + (32 + ch) * kXP + p4) = v;
            }
            if (tid < 128) {
                int g = tid >> 4, p4 = (tid & 15) * 4;
                const float* mp = mem + (size_t)(m * 64 + 4 * g) * kHW + p0 + p4;
                float4 v0 = *(const float4*)(mp);
                float4 v1 = *(const float4*)(mp + kHW);
                float4 v2 = *(const float4*)(mp + 2 * kHW);
                float4 v3 = *(const float4*)(mp + 3 * kHW);
                #pragma unroll
                for (int r = 0; r < 4; r++) {
                    float a0 = sxf[r * 4 + 0], a1 = sxf[r * 4 + 1];
                    float a2 = sxf[r * 4 + 2], a3 = sxf[r * 4 + 3];
                    float4 o;
                    o.x = a0 * v0.x + a1 * v1.x + a2 * v2.x + a3 * v3.x;
                    o.y = a0 * v0.y + a1 * v1.y + a2 * v2.y + a3 * v3.y;
                    o.z = a0 * v0.z + a1 * v1.z + a2 * v2.z + a3 * v3.z;
                    o.w = a0 * v0.w + a1 * v1.w + a2 * v2.w + a3 * v3.w;
                    *(float4*)(xs + (4 * g + r) * kXP + p4) = o;
                }
            }
        } else {
            for (int i = tid; i < 64 * 16; i += kTHREADS)
                *(float4*)(xs + (i >> 4) * kXP + (i & 15) * 4) =
                    make_float4(0.f, 0.f, 0.f, 0.f);
        }
        __syncthreads();

        // ---- layers 0,1: 128x128 GEMM + bias + relu, in-place on xs ----
        #pragma unroll 1
        for (int l = 0; l < 2; l++) {
            const float* Wt = l ? Wt1 : Wt0;
            const float bias = sb[l * 128 + c];
            u64 acc[16];
            u64 bini = pack2(bias, bias);
            #pragma unroll
            for (int q = 0; q < 16; q++) acc[q] = bini;

            const float* xbase = xs + half * 32;
            #pragma unroll 2
            for (int k = 0; k < 128; k++) {
                float w = Wt[k * kWP + c];
                u64 wp = pack2(w, w);
                const ulonglong2* xk = (const ulonglong2*)(xbase + k * kXP);
                #pragma unroll
                for (int q = 0; q < 8; q++) {
                    ulonglong2 v = xk[q];
                    fma2(acc[2 * q],     wp, v.x);
                    fma2(acc[2 * q + 1], wp, v.y);
                }
            }
            __syncthreads();
            float* orow = xs + c * kXP + half * 32;
            #pragma unroll
            for (int q = 0; q < 16; q++) {
                float2 f = unpack2(acc[q]);
                ((float2*)orow)[q] = make_float2(fmaxf(f.x, 0.f), fmaxf(f.y, 0.f));
            }
            __syncthreads();
        }

        // ---- layer 2: 64 outputs (ch 64..127), bias, straight to gmem ----
        {
            const float bias = sb[256 + 64 + c2];
            u64 acc[8];
            u64 bini = pack2(bias, bias);
            #pragma unroll
            for (int q = 0; q < 8; q++) acc[q] = bini;

            const float* xbase = xs + quad * 16;
            #pragma unroll 2
            for (int k = 0; k < 128; k++) {
                float w = Wt2[k * kWP2 + c2];
                u64 wp = pack2(w, w);
                const ulonglong2* xk = (const ulonglong2*)(xbase + k * kXP);
                #pragma unroll
                for (int q = 0; q < 4; q++) {
                    ulonglong2 v = xk[q];
                    fma2(acc[2 * q],     wp, v.x);
                    fma2(acc[2 * q + 1], wp, v.y);
                }
            }
            float* op = out + (size_t)(b * 64 + c2) * kHW + p0 + quad * 16;
            #pragma unroll
            for (int q = 0; q < 4; q++) {
                float2 fa = unpack2(acc[2 * q]);
                float2 fb = unpack2(acc[2 * q + 1]);
                ((float4*)op)[q] = make_float4(fa.x, fa.y, fb.x, fb.y);
            }
        }
        // loop-head __syncthreads protects xs for next tile's staging
    }
}

// ---------------------------------------------------------------------------
// Launcher. Inputs (metadata order):
// 0 img_features (B,64,H,W) f32     1 prev_mem_features (M,64,H,W) f32
// 2 prev_extrinsics (M,4,4) f32     3 cur_extrinsics (B,4,4) f32
// 4 memory_idx (B,) i32             5 use_memory (B,) bool
// 6 Ws (3,128,128) f32              7 bs (3,128) f32
// Output: (B,64,H,W) f32
// ---------------------------------------------------------------------------
extern "C" void kernel_launch(void* const* d_in, const int* in_sizes, int n_in,
                              void* d_out, int out_size) {
    const float* img      = (const float*)d_in[0];
    const float* mem      = (const float*)d_in[1];
    const float* prev_ext = (const float*)d_in[2];
    const float* cur_ext  = (const float*)d_in[3];
    const int*   midx     = (const int*)d_in[4];
    const unsigned char* use_raw = (const unsigned char*)d_in[5];
    const float* Ws       = (const float*)d_in[6];
    const float* bs       = (const float*)d_in[7];
    float*       out      = (float*)d_out;

    static int nsm = 0;
    if (nsm == 0) {
        int dev = 0;
        cudaGetDevice(&dev);
        cudaDeviceGetAttribute(&nsm, cudaDevAttrMultiProcessorCount, dev);
        if (nsm <= 0) nsm = 148;
        cudaFuncSetAttribute(fused_kernel,
                             cudaFuncAttributeMaxDynamicSharedMemorySize,
                             (int)SMEM_BYTES);
    }

    prep_kernel<<<1, 32>>>(prev_ext, cur_ext, midx, use_raw);
    fused_kernel<<<nsm, kTHREADS, SMEM_BYTES>>>(img, mem, Ws, bs, out);
}

// round 2
// speedup vs baseline: 1.3659x; 1.3659x over previous
#include <cuda_runtime.h>
#include <cstdint>
#include <math.h>

// ---------------------------------------------------------------------------
// SimpleConvRNN fused kernel for GB300 (sm_103a) — round 2
// Register-blocked (4ch x 8px per thread) fp32x2 FMA GEMMs, 384 threads,
// persistent CTAs, all weights resident in SMEM (transposed).
// ---------------------------------------------------------------------------

namespace {
constexpr int kB       = 32;
constexpr int kHW      = 64 * 96;          // 6144
constexpr int kTP      = 96;               // pixels per tile
constexpr int kTHREADS = 384;
constexpr int kTilesPerB = kHW / kTP;      // 64
constexpr int kNTiles  = kB * kTilesPerB;  // 2048
constexpr int kXP      = 100;              // xs pitch (floats), 400B (16B-aligned)

constexpr int W0_OFF = 0;                  // [k][o] pitch 128
constexpr int W1_OFF = W0_OFF + 128 * 128;
constexpr int W2_OFF = W1_OFF + 128 * 128; // [k][o2] pitch 64 (out ch 64..127)
constexpr int XS_OFF = W2_OFF + 128 * 64;  // [ch][px] pitch 100
constexpr int SB_OFF = XS_OFF + 128 * kXP;
constexpr int XF_OFF = SB_OFF + 384;
constexpr int SMEM_FLOATS = XF_OFF + 16;
constexpr size_t SMEM_BYTES = (size_t)SMEM_FLOATS * sizeof(float); // ~211.6 KB
}

typedef unsigned long long u64;

__device__ __forceinline__ u64 pack2(float a, float b) {
    u64 r;
    asm("mov.b64 %0, {%1, %2};" : "=l"(r) : "f"(a), "f"(b));
    return r;
}
__device__ __forceinline__ void fma2(u64& d, u64 a, u64 b) {
    asm("fma.rn.f32x2 %0, %1, %2, %0;" : "+l"(d) : "l"(a), "l"(b));
}
__device__ __forceinline__ float2 unpack2(u64 v) {
    float2 f;
    asm("mov.b64 {%0, %1}, %2;" : "=f"(f.x), "=f"(f.y) : "l"(v));
    return f;
}

__device__ float g_xf[kB * 16];
__device__ int   g_use[kB];
__device__ int   g_midx[kB];

// ---------------------------------------------------------------------------
// Prep: decode use_memory, 4x4 inverse, xf = cur @ inv(prev). (unchanged, R1 OK)
// ---------------------------------------------------------------------------
__global__ void prep_kernel(const float* __restrict__ prev_ext,
                            const float* __restrict__ cur_ext,
                            const int*   __restrict__ memory_idx,
                            const unsigned char* __restrict__ use_raw) {
    int b = threadIdx.x;
    if (b >= kB) return;

    const unsigned int* w32 = (const unsigned int*)use_raw;
    bool int_layout = true, float_layout = true;
    #pragma unroll
    for (int i = 0; i < 8; i++) {
        unsigned int v = w32[i];
        if (v != 0u && v != 1u)          int_layout = false;
        if (v != 0u && v != 0x3f800000u) float_layout = false;
    }
    int use;
    if (int_layout || float_layout) use = (w32[b] != 0u) ? 1 : 0;
    else                            use = use_raw[b] ? 1 : 0;
    g_use[b] = use;

    int m = memory_idx[b];
    g_midx[b] = m;

    float A[4][8];
    #pragma unroll
    for (int r = 0; r < 4; r++)
        #pragma unroll
        for (int c = 0; c < 4; c++) {
            A[r][c]     = use ? prev_ext[(size_t)m * 16 + r * 4 + c]
                              : (r == c ? 1.f : 0.f);
            A[r][c + 4] = (r == c) ? 1.f : 0.f;
        }
    for (int col = 0; col < 4; col++) {
        int piv = col;
        float best = fabsf(A[col][col]);
        for (int r = col + 1; r < 4; r++) {
            float v = fabsf(A[r][col]);
            if (v > best) { best = v; piv = r; }
        }
        if (piv != col)
            for (int j = 0; j < 8; j++) {
                float t = A[col][j]; A[col][j] = A[piv][j]; A[piv][j] = t;
            }
        float inv = 1.f / A[col][col];
        for (int j = 0; j < 8; j++) A[col][j] *= inv;
        for (int r = 0; r < 4; r++) {
            if (r == col) continue;
            float f = A[r][col];
            for (int j = 0; j < 8; j++) A[r][j] -= f * A[col][j];
        }
    }
    #pragma unroll
    for (int i = 0; i < 4; i++)
        #pragma unroll
        for (int j = 0; j < 4; j++) {
            float s = 0.f;
            #pragma unroll
            for (int k = 0; k < 4; k++)
                s += cur_ext[(size_t)b * 16 + i * 4 + k] * A[k][4 + j];
            g_xf[b * 16 + i * 4 + j] = s;
        }
}

// ---------------------------------------------------------------------------
// Main fused kernel
// ---------------------------------------------------------------------------
__global__ void __launch_bounds__(kTHREADS, 1)
fused_kernel(const float* __restrict__ img,
             const float* __restrict__ mem,
             const float* __restrict__ Ws,
             const float* __restrict__ bs,
             float* __restrict__ out) {
    extern __shared__ float sm[];
    float* Wt0 = sm + W0_OFF;
    float* Wt1 = sm + W1_OFF;
    float* Wt2 = sm + W2_OFF;
    float* xs  = sm + XS_OFF;
    float* sb  = sm + SB_OFF;
    float* sxf = sm + XF_OFF;

    const int tid = threadIdx.x;

    // ---- one-time weight staging (transposed: [k][o]) ----
    for (int i = tid; i < 128 * 128; i += kTHREADS) {
        int o = i >> 7, k = i & 127;
        Wt0[k * 128 + o] = Ws[i];
        Wt1[k * 128 + o] = Ws[16384 + i];
    }
    for (int i = tid; i < 64 * 128; i += kTHREADS) {
        int o = i >> 7, k = i & 127;              // o: 0..63 -> out ch 64+o
        Wt2[k * 64 + o] = Ws[2 * 16384 + (64 + o) * 128 + k];
    }
    for (int i = tid; i < 384; i += kTHREADS) sb[i] = bs[i];
    __syncthreads();

    const int cg  = tid & 31;        // channel group (layers 0,1: 4 ch; layer 2: 2 ch)
    const int c4  = cg * 4;
    const int o2  = cg * 2;
    const int pg  = tid >> 5;        // pixel group 0..11 (8 px each)
    const int px  = pg * 8;

    for (int t = blockIdx.x; t < kNTiles; t += gridDim.x) {
        const int b  = t >> 6;                 // kTilesPerB = 64
        const int p0 = (t & 63) * kTP;

        if (tid < 16) sxf[tid] = g_xf[b * 16 + tid];
        const int useb = g_use[b];
        const int m    = g_midx[b];
        __syncthreads();   // xs reuse safe + sxf visible

        // ---- stage x tile (96 px): ch 64..127 = img ----
        for (int i = tid; i < 64 * 24; i += kTHREADS) {     // 1536 items, 4/thread
            int ch = i / 24, j4 = (i % 24) * 4;
            float4 v = *(const float4*)(img + (size_t)(b * 64 + ch) * kHW + p0 + j4);
            *(float4*)(xs + (64 + ch) * kXP + j4) = v;
        }
        if (useb) {
            // ch 32..63 straight copy from mem
            for (int i = tid; i < 32 * 24; i += kTHREADS) { // 768 items
                int ch = i / 24, j4 = (i % 24) * 4;
                float4 v = *(const float4*)(mem + (size_t)(m * 64 + 32 + ch) * kHW + p0 + j4);
                *(float4*)(xs + (32 + ch) * kXP + j4) = v;
            }
            // ch 0..31: FTL 4x4 transform, 8 groups x 24 float4 = 192 items
            if (tid < 192) {
                int g = tid / 24, j4 = (tid % 24) * 4;
                const float* mp = mem + (size_t)(m * 64 + 4 * g) * kHW + p0 + j4;
                float4 v0 = *(const float4*)(mp);
                float4 v1 = *(const float4*)(mp + kHW);
                float4 v2 = *(const float4*)(mp + 2 * kHW);
                float4 v3 = *(const float4*)(mp + 3 * kHW);
                #pragma unroll
                for (int r = 0; r < 4; r++) {
                    float a0 = sxf[r * 4 + 0], a1 = sxf[r * 4 + 1];
                    float a2 = sxf[r * 4 + 2], a3 = sxf[r * 4 + 3];
                    float4 o;
                    o.x = a0 * v0.x + a1 * v1.x + a2 * v2.x + a3 * v3.x;
                    o.y = a0 * v0.y + a1 * v1.y + a2 * v2.y + a3 * v3.y;
                    o.z = a0 * v0.z + a1 * v1.z + a2 * v2.z + a3 * v3.z;
                    o.w = a0 * v0.w + a1 * v1.w + a2 * v2.w + a3 * v3.w;
                    *(float4*)(xs + (4 * g + r) * kXP + j4) = o;
                }
            }
        } else {
            for (int i = tid; i < 64 * 24; i += kTHREADS)
                *(float4*)(xs + (i / 24) * kXP + (i % 24) * 4) =
                    make_float4(0.f, 0.f, 0.f, 0.f);
        }
        __syncthreads();

        // ---- layers 0,1: 128x128 GEMM + bias + relu, in-place on xs ----
        #pragma unroll 1
        for (int l = 0; l < 2; l++) {
            const float* Wt = l ? Wt1 : Wt0;
            u64 acc[16];
            #pragma unroll
            for (int r = 0; r < 4; r++) {
                float bv = sb[l * 128 + c4 + r];
                u64 bb = pack2(bv, bv);
                acc[r * 4 + 0] = bb; acc[r * 4 + 1] = bb;
                acc[r * 4 + 2] = bb; acc[r * 4 + 3] = bb;
            }
            const float* wb = Wt + c4;
            const float* xb = xs + px;
            #pragma unroll 2
            for (int k = 0; k < 128; k++) {
                float4 wv = *(const float4*)(wb + k * 128);
                ulonglong2 xa = *(const ulonglong2*)(xb + (size_t)k * kXP);
                ulonglong2 xc = *(const ulonglong2*)(xb + (size_t)k * kXP + 4);
                u64 w0 = pack2(wv.x, wv.x);
                u64 w1 = pack2(wv.y, wv.y);
                u64 w2 = pack2(wv.z, wv.z);
                u64 w3 = pack2(wv.w, wv.w);
                fma2(acc[0],  w0, xa.x); fma2(acc[1],  w0, xa.y);
                fma2(acc[2],  w0, xc.x); fma2(acc[3],  w0, xc.y);
                fma2(acc[4],  w1, xa.x); fma2(acc[5],  w1, xa.y);
                fma2(acc[6],  w1, xc.x); fma2(acc[7],  w1, xc.y);
                fma2(acc[8],  w2, xa.x); fma2(acc[9],  w2, xa.y);
                fma2(acc[10], w2, xc.x); fma2(acc[11], w2, xc.y);
                fma2(acc[12], w3, xa.x); fma2(acc[13], w3, xa.y);
                fma2(acc[14], w3, xc.x); fma2(acc[15], w3, xc.y);
            }
            __syncthreads();
            #pragma unroll
            for (int r = 0; r < 4; r++) {
                float* row = xs + (c4 + r) * kXP + px;
                float2 f0 = unpack2(acc[r * 4 + 0]);
                float2 f1 = unpack2(acc[r * 4 + 1]);
                float2 f2 = unpack2(acc[r * 4 + 2]);
                float2 f3 = unpack2(acc[r * 4 + 3]);
                ((float4*)row)[0] = make_float4(fmaxf(f0.x, 0.f), fmaxf(f0.y, 0.f),
                                                fmaxf(f1.x, 0.f), fmaxf(f1.y, 0.f));
                ((float4*)row)[1] = make_float4(fmaxf(f2.x, 0.f), fmaxf(f2.y, 0.f),
                                                fmaxf(f3.x, 0.f), fmaxf(f3.y, 0.f));
            }
            __syncthreads();
        }

        // ---- layer 2: 64 outputs (out ch 64..127), bias, write gmem ----
        {
            u64 acc[8];
            #pragma unroll
            for (int r = 0; r < 2; r++) {
                float bv = sb[256 + 64 + o2 + r];
                u64 bb = pack2(bv, bv);
                acc[r * 4 + 0] = bb; acc[r * 4 + 1] = bb;
                acc[r * 4 + 2] = bb; acc[r * 4 + 3] = bb;
            }
            const float* wb = Wt2 + o2;
            const float* xb = xs + px;
            #pragma unroll 2
            for (int k = 0; k < 128; k++) {
                float2 wv = *(const float2*)(wb + k * 64);
                ulonglong2 xa = *(const ulonglong2*)(xb + (size_t)k * kXP);
                ulonglong2 xc = *(const ulonglong2*)(xb + (size_t)k * kXP + 4);
                u64 w0 = pack2(wv.x, wv.x);
                u64 w1 = pack2(wv.y, wv.y);
                fma2(acc[0], w0, xa.x); fma2(acc[1], w0, xa.y);
                fma2(acc[2], w0, xc.x); fma2(acc[3], w0, xc.y);
                fma2(acc[4], w1, xa.x); fma2(acc[5], w1, xa.y);
                fma2(acc[6], w1, xc.x); fma2(acc[7], w1, xc.y);
            }
            #pragma unroll
            for (int r = 0; r < 2; r++) {
                float* op = out + (size_t)(b * 64 + o2 + r) * kHW + p0 + px;
                float2 f0 = unpack2(acc[r * 4 + 0]);
                float2 f1 = unpack2(acc[r * 4 + 1]);
                float2 f2 = unpack2(acc[r * 4 + 2]);
                float2 f3 = unpack2(acc[r * 4 + 3]);
                ((float4*)op)[0] = make_float4(f0.x, f0.y, f1.x, f1.y);
                ((float4*)op)[1] = make_float4(f2.x, f2.y, f3.x, f3.y);
            }
        }
        // loop-head __syncthreads protects xs for next tile
    }
}

// ---------------------------------------------------------------------------
extern "C" void kernel_launch(void* const* d_in, const int* in_sizes, int n_in,
                              void* d_out, int out_size) {
    const float* img      = (const float*)d_in[0];
    const float* mem      = (const float*)d_in[1];
    const float* prev_ext = (const float*)d_in[2];
    const float* cur_ext  = (const float*)d_in[3];
    const int*   midx     = (const int*)d_in[4];
    const unsigned char* use_raw = (const unsigned char*)d_in[5];
    const float* Ws       = (const float*)d_in[6];
    const float* bs       = (const float*)d_in[7];
    float*       out      = (float*)d_out;

    static int nsm = 0;
    if (nsm == 0) {
        int dev = 0;
        cudaGetDevice(&dev);
        cudaDeviceGetAttribute(&nsm, cudaDevAttrMultiProcessorCount, dev);
        if (nsm <= 0) nsm = 148;
        cudaFuncSetAttribute(fused_kernel,
                             cudaFuncAttributeMaxDynamicSharedMemorySize,
                             (int)SMEM_BYTES);
    }

    prep_kernel<<<1, 32>>>(prev_ext, cur_ext, midx, use_raw);
    fused_kernel<<<nsm, kTHREADS, SMEM_BYTES>>>(img, mem, Ws, bs, out);
}

// round 4
// speedup vs baseline: 1.7572x; 1.2865x over previous
#include <cuda_runtime.h>
#include <mma.h>
#include <cstdint>
#include <math.h>

using namespace nvcuda;

// ---------------------------------------------------------------------------
// SimpleConvRNN fused kernel for GB300 (sm_103a) — round 4: wmma tf32
// (tcgen05 unreachable: harness compiles via compute_103 base target).
// Persistent CTAs, weights resident in SMEM transposed [k][out], x tile
// [k][px] (ld=100). 3 chained GEMMs per 96-px tile via wmma m16n16k8 tf32.
// ---------------------------------------------------------------------------

namespace {
constexpr int kB   = 32;
constexpr int kHW  = 6144;
constexpr int kTP  = 96;                    // pixels per tile
constexpr int kTilesPerB = kHW / kTP;       // 64
constexpr int kNTiles = kB * kTilesPerB;    // 2048
constexpr int kTHREADS = 384;

constexpr int kLDW  = 132;                  // W0/W1 pitch [k][out]
constexpr int kLDW2 = 68;                   // W2 pitch [k][out2]
constexpr int kLDX  = 100;                  // xs pitch [k][px]

constexpr int W0F = 0;                      // 128 x 132
constexpr int W1F = W0F + 128 * kLDW;       // 16896
constexpr int W2F = W1F + 128 * kLDW;       // 136 x 68 (k rows incl. bias row)
constexpr int XSF = W2F + 136 * kLDW2;      // 136 x 100
constexpr int SBF = XSF + 136 * kLDX;       // 256 biases (layers 0,1)
constexpr int XFF = SBF + 256;              // 16 xf
constexpr int TOTF = XFF + 16;
constexpr size_t SMEM_BYTES = (size_t)TOTF * 4;   // 227,712 B < 232,448 B
}

__device__ __forceinline__ float totf32(float x) {
    float r;
    asm("cvt.rna.tf32.f32 %0, %1;" : "=f"(r) : "f"(x));
    return r;
}

__device__ float g_xf[kB * 16];
__device__ int   g_use[kB];
__device__ int   g_midx[kB];

// ---------------------------------------------------------------------------
__global__ void prep_kernel(const float* __restrict__ prev_ext,
                            const float* __restrict__ cur_ext,
                            const int*   __restrict__ memory_idx,
                            const unsigned char* __restrict__ use_raw) {
    int b = threadIdx.x;
    if (b >= kB) return;

    const unsigned int* w32 = (const unsigned int*)use_raw;
    bool int_layout = true, float_layout = true;
    #pragma unroll
    for (int i = 0; i < 8; i++) {
        unsigned int v = w32[i];
        if (v != 0u && v != 1u)          int_layout = false;
        if (v != 0u && v != 0x3f800000u) float_layout = false;
    }
    int use;
    if (int_layout || float_layout) use = (w32[b] != 0u) ? 1 : 0;
    else                            use = use_raw[b] ? 1 : 0;
    g_use[b] = use;
    int m = memory_idx[b];
    g_midx[b] = m;

    float A[4][8];
    #pragma unroll
    for (int r = 0; r < 4; r++)
        #pragma unroll
        for (int c = 0; c < 4; c++) {
            A[r][c]     = use ? prev_ext[(size_t)m * 16 + r * 4 + c]
                              : (r == c ? 1.f : 0.f);
            A[r][c + 4] = (r == c) ? 1.f : 0.f;
        }
    for (int col = 0; col < 4; col++) {
        int piv = col;
        float best = fabsf(A[col][col]);
        for (int r = col + 1; r < 4; r++) {
            float v = fabsf(A[r][col]);
            if (v > best) { best = v; piv = r; }
        }
        if (piv != col)
            for (int j = 0; j < 8; j++) {
                float t = A[col][j]; A[col][j] = A[piv][j]; A[piv][j] = t;
            }
        float inv = 1.f / A[col][col];
        for (int j = 0; j < 8; j++) A[col][j] *= inv;
        for (int r = 0; r < 4; r++) {
            if (r == col) continue;
            float f = A[r][col];
            for (int j = 0; j < 8; j++) A[r][j] -= f * A[col][j];
        }
    }
    #pragma unroll
    for (int i = 0; i < 4; i++)
        #pragma unroll
        for (int j = 0; j < 4; j++) {
            float s = 0.f;
            #pragma unroll
            for (int k = 0; k < 4; k++)
                s += cur_ext[(size_t)b * 16 + i * 4 + k] * A[k][4 + j];
            g_xf[b * 16 + i * 4 + j] = s;
        }
}

// ---------------------------------------------------------------------------
using FragA = wmma::fragment<wmma::matrix_a, 16, 16, 8,
                             wmma::precision::tf32, wmma::col_major>;
using FragB = wmma::fragment<wmma::matrix_b, 16, 16, 8,
                             wmma::precision::tf32, wmma::row_major>;
using FragC = wmma::fragment<wmma::accumulator, 16, 16, 8, float>;

__global__ void __launch_bounds__(kTHREADS, 1)
fused_kernel(const float* __restrict__ img,
             const float* __restrict__ mem,
             const float* __restrict__ Ws,
             const float* __restrict__ bs,
             float* __restrict__ out) {
    extern __shared__ float sm[];
    float* W0 = sm + W0F;    // [k][out] ld 132
    float* W1 = sm + W1F;
    float* W2 = sm + W2F;    // [k][out2] ld 68, 136 k-rows (row 128 = bias)
    float* xs = sm + XSF;    // [k][px]  ld 100, 136 k-rows (row 128 = ones)
    float* sb = sm + SBF;
    float* sxf = sm + XFF;

    const int tid = threadIdx.x;
    const int wid = tid >> 5;

    // ---- one-time staging: weights (transposed, tf32-rounded) ----
    for (int i = tid; i < 128 * 128; i += kTHREADS) {
        int o = i >> 7, k = i & 127;                  // coalesced read
        W0[k * kLDW + o] = totf32(Ws[o * 128 + k]);
        W1[k * kLDW + o] = totf32(Ws[16384 + o * 128 + k]);
    }
    for (int i = tid; i < 64 * 128; i += kTHREADS) {
        int o = i >> 7, k = i & 127;                  // out ch 64+o of layer 2
        W2[k * kLDW2 + o] = totf32(Ws[2 * 16384 + (64 + o) * 128 + k]);
    }
    // W2 bias row (k=128) + zero rows 129..135
    for (int i = tid; i < 8 * kLDW2; i += kTHREADS) {
        int r = i / kLDW2, c = i % kLDW2;
        W2[(128 + r) * kLDW2 + c] =
            (r == 0 && c < 64) ? totf32(bs[256 + 64 + c]) : 0.f;
    }
    // xs ones row (k=128) + zero rows 129..135
    for (int i = tid; i < 8 * kLDX; i += kTHREADS) {
        int r = i / kLDX, c = i % kLDX;
        xs[(128 + r) * kLDX + c] = (r == 0) ? 1.f : 0.f;
    }
    for (int i = tid; i < 256; i += kTHREADS) sb[i] = bs[i];
    __syncthreads();

    // warp tiling: 12 warps = 3 px-groups (32 px) x 4 out-groups
    const int pxg  = wid % 3;
    const int outg = wid / 3;
    const int px0  = pxg * 32;

    for (int t = blockIdx.x; t < kNTiles; t += gridDim.x) {
        const int b  = t >> 6;
        const int p0 = (t & 63) * kTP;

        if (tid < 16) sxf[tid] = g_xf[b * 16 + tid];
        const int useb = g_use[b];
        const int m    = g_midx[b];
        __syncthreads();   // prev tile done with xs; sxf visible

        // ---- stage x tile (rows 0..127 of xs), tf32-rounded ----
        for (int i = tid; i < 64 * 24; i += kTHREADS) {         // img -> 64..127
            int ch = i / 24, j4 = (i % 24) * 4;
            const float* p = img + (size_t)(b * 64 + ch) * kHW + p0 + j4;
            float4 v = *(const float4*)p;
            *(float4*)(xs + (64 + ch) * kLDX + j4) =
                make_float4(totf32(v.x), totf32(v.y), totf32(v.z), totf32(v.w));
        }
        if (useb) {
            for (int i = tid; i < 32 * 24; i += kTHREADS) {     // mem -> 32..63
                int ch = i / 24, j4 = (i % 24) * 4;
                const float* p = mem + (size_t)(m * 64 + 32 + ch) * kHW + p0 + j4;
                float4 v = *(const float4*)p;
                *(float4*)(xs + (32 + ch) * kLDX + j4) =
                    make_float4(totf32(v.x), totf32(v.y), totf32(v.z), totf32(v.w));
            }
            if (tid < 192) {                                    // FTL -> 0..31
                int g = tid / 24, j4 = (tid % 24) * 4;
                const float* mp = mem + (size_t)(m * 64 + 4 * g) * kHW + p0 + j4;
                float4 v0 = *(const float4*)(mp);
                float4 v1 = *(const float4*)(mp + kHW);
                float4 v2 = *(const float4*)(mp + 2 * kHW);
                float4 v3 = *(const float4*)(mp + 3 * kHW);
                #pragma unroll
                for (int r = 0; r < 4; r++) {
                    float a0 = sxf[r*4+0], a1 = sxf[r*4+1];
                    float a2 = sxf[r*4+2], a3 = sxf[r*4+3];
                    *(float4*)(xs + (4 * g + r) * kLDX + j4) = make_float4(
                        totf32(a0*v0.x + a1*v1.x + a2*v2.x + a3*v3.x),
                        totf32(a0*v0.y + a1*v1.y + a2*v2.y + a3*v3.y),
                        totf32(a0*v0.z + a1*v1.z + a2*v2.z + a3*v3.z),
                        totf32(a0*v0.w + a1*v1.w + a2*v2.w + a3*v3.w));
                }
            }
        } else {
            for (int i = tid; i < 64 * 24; i += kTHREADS)
                *(float4*)(xs + (i / 24) * kLDX + (i % 24) * 4) =
                    make_float4(0.f, 0.f, 0.f, 0.f);
        }
        __syncthreads();

        // ---- layers 0,1: Y[px][out] = Xt @ Wt, K=128; in-place on xs ----
        #pragma unroll 1
        for (int l = 0; l < 2; l++) {
            const float* W = l ? W1 : W0;
            const int out0 = outg * 32;

            FragC c[2][2];
            #pragma unroll
            for (int i = 0; i < 2; i++)
                #pragma unroll
                for (int j = 0; j < 2; j++)
                    wmma::fill_fragment(c[i][j], 0.f);

            #pragma unroll 4
            for (int k0 = 0; k0 < 128; k0 += 8) {
                FragA a[2];
                FragB bfr[2];
                wmma::load_matrix_sync(a[0], xs + px0      + k0 * kLDX, kLDX);
                wmma::load_matrix_sync(a[1], xs + px0 + 16 + k0 * kLDX, kLDX);
                wmma::load_matrix_sync(bfr[0], W + k0 * kLDW + out0,      kLDW);
                wmma::load_matrix_sync(bfr[1], W + k0 * kLDW + out0 + 16, kLDW);
                #pragma unroll
                for (int i = 0; i < 2; i++)
                    #pragma unroll
                    for (int j = 0; j < 2; j++)
                        wmma::mma_sync(c[i][j], a[i], bfr[j], c[i][j]);
            }
            __syncthreads();   // all reads of xs done
            #pragma unroll
            for (int i = 0; i < 2; i++)
                #pragma unroll
                for (int j = 0; j < 2; j++)
                    wmma::store_matrix_sync(
                        xs + (out0 + 16 * j) * kLDX + px0 + 16 * i,
                        c[i][j], kLDX, wmma::mem_col_major);
            __syncthreads();

            // bias + relu + tf32 re-round, in place (rows 0..127)
            for (int i = tid; i < 128 * 24; i += kTHREADS) {
                int o = i / 24, j4 = (i % 24) * 4;
                float bias = sb[l * 128 + o];
                float4 v = *(const float4*)(xs + o * kLDX + j4);
                *(float4*)(xs + o * kLDX + j4) = make_float4(
                    totf32(fmaxf(v.x + bias, 0.f)),
                    totf32(fmaxf(v.y + bias, 0.f)),
                    totf32(fmaxf(v.z + bias, 0.f)),
                    totf32(fmaxf(v.w + bias, 0.f)));
            }
            __syncthreads();
        }

        // ---- layer 2: K=136 (row 128 = ones x bias), out2 = 64, to gmem ----
        {
            const int out0 = outg * 16;
            FragC c2[2];
            wmma::fill_fragment(c2[0], 0.f);
            wmma::fill_fragment(c2[1], 0.f);

            #pragma unroll 4
            for (int k0 = 0; k0 < 136; k0 += 8) {
                FragA a[2];
                FragB bfr;
                wmma::load_matrix_sync(a[0], xs + px0      + k0 * kLDX, kLDX);
                wmma::load_matrix_sync(a[1], xs + px0 + 16 + k0 * kLDX, kLDX);
                wmma::load_matrix_sync(bfr, W2 + k0 * kLDW2 + out0, kLDW2);
                wmma::mma_sync(c2[0], a[0], bfr, c2[0]);
                wmma::mma_sync(c2[1], a[1], bfr, c2[1]);
            }
            float* op = out + (size_t)(b * 64 + out0) * kHW + p0 + px0;
            wmma::store_matrix_sync(op,      c2[0], kHW, wmma::mem_col_major);
            wmma::store_matrix_sync(op + 16, c2[1], kHW, wmma::mem_col_major);
        }
        // loop-head __syncthreads guards xs restaging
    }
}

// ---------------------------------------------------------------------------
extern "C" void kernel_launch(void* const* d_in, const int* in_sizes, int n_in,
                              void* d_out, int out_size) {
    const float* img      = (const float*)d_in[0];
    const float* mem      = (const float*)d_in[1];
    const float* prev_ext = (const float*)d_in[2];
    const float* cur_ext  = (const float*)d_in[3];
    const int*   midx     = (const int*)d_in[4];
    const unsigned char* use_raw = (const unsigned char*)d_in[5];
    const float* Ws       = (const float*)d_in[6];
    const float* bs       = (const float*)d_in[7];
    float*       out      = (float*)d_out;

    static int nsm = 0;
    if (nsm == 0) {
        int dev = 0;
        cudaGetDevice(&dev);
        cudaDeviceGetAttribute(&nsm, cudaDevAttrMultiProcessorCount, dev);
        if (nsm <= 0) nsm = 148;
        cudaFuncSetAttribute(fused_kernel,
                             cudaFuncAttributeMaxDynamicSharedMemorySize,
                             (int)SMEM_BYTES);
    }

    prep_kernel<<<1, 32>>>(prev_ext, cur_ext, midx, use_raw);
    fused_kernel<<<nsm, kTHREADS, SMEM_BYTES>>>(img, mem, Ws, bs, out);
}

// round 6
// speedup vs baseline: 5.8531x; 3.3309x over previous
#include <cuda_runtime.h>
#include <cuda_fp16.h>
#include <mma.h>
#include <cstdint>
#include <math.h>

using namespace nvcuda;

// ---------------------------------------------------------------------------
// SimpleConvRNN fused kernel for GB300 (sm_103a) — round 6: wmma fp16 MMA
// (fp32 accum). R5 + fix: use_memory==false zero-fill indexing covered only
// part of rows 0..63 (stale smem -> 0.166 rel_err). Now exact.
// ---------------------------------------------------------------------------

namespace {
constexpr int kB   = 32;
constexpr int kHW  = 6144;
constexpr int kTP  = 128;                   // pixels per tile
constexpr int kTilesPerB = kHW / kTP;       // 48
constexpr int kNTiles = kB * kTilesPerB;    // 1536
constexpr int kTHREADS = 512;

constexpr int kLDX  = 136;                  // xs pitch (halves)
constexpr int kLDW  = 136;                  // W0/W1 pitch (halves)
constexpr int kLDW2 = 72;                   // W2 pitch (halves)
constexpr int kLDY  = 132;                  // ys pitch (floats)

// float-indexed smem offsets (all 16B-aligned)
constexpr int W0F = 0;                      // 128 x 136 halves = 8704 f
constexpr int W1F = W0F + 8704;
constexpr int W2F = W1F + 8704;             // 144 x 72 halves = 5184 f
constexpr int XSF = W2F + 5184;             // 144 x 136 halves = 9792 f
constexpr int YSF = XSF + 9792;             // 128 x 132 floats = 16896 f
constexpr int SBF = YSF + 16896;            // 256 biases (L0,L1)
constexpr int XFF = SBF + 256;              // 16 xf
constexpr int TOTF = XFF + 16;
constexpr size_t SMEM_BYTES = (size_t)TOTF * 4;   // ~198 KB
}

__device__ __forceinline__ void st_half4(__half* p, float a, float b,
                                         float c, float d) {
    __half2 lo = __floats2half2_rn(a, b);
    __half2 hi = __floats2half2_rn(c, d);
    uint2 v;
    v.x = *(uint32_t*)&lo;
    v.y = *(uint32_t*)&hi;
    *(uint2*)p = v;
}

__device__ float g_xf[kB * 16];
__device__ int   g_use[kB];
__device__ int   g_midx[kB];

// ---------------------------------------------------------------------------
__global__ void prep_kernel(const float* __restrict__ prev_ext,
                            const float* __restrict__ cur_ext,
                            const int*   __restrict__ memory_idx,
                            const unsigned char* __restrict__ use_raw) {
    int b = threadIdx.x;
    if (b >= kB) return;

    const unsigned int* w32 = (const unsigned int*)use_raw;
    bool int_layout = true, float_layout = true;
    #pragma unroll
    for (int i = 0; i < 8; i++) {
        unsigned int v = w32[i];
        if (v != 0u && v != 1u)          int_layout = false;
        if (v != 0u && v != 0x3f800000u) float_layout = false;
    }
    int use;
    if (int_layout || float_layout) use = (w32[b] != 0u) ? 1 : 0;
    else                            use = use_raw[b] ? 1 : 0;
    g_use[b] = use;
    int m = memory_idx[b];
    g_midx[b] = m;

    float A[4][8];
    #pragma unroll
    for (int r = 0; r < 4; r++)
        #pragma unroll
        for (int c = 0; c < 4; c++) {
            A[r][c]     = use ? prev_ext[(size_t)m * 16 + r * 4 + c]
                              : (r == c ? 1.f : 0.f);
            A[r][c + 4] = (r == c) ? 1.f : 0.f;
        }
    for (int col = 0; col < 4; col++) {
        int piv = col;
        float best = fabsf(A[col][col]);
        for (int r = col + 1; r < 4; r++) {
            float v = fabsf(A[r][col]);
            if (v > best) { best = v; piv = r; }
        }
        if (piv != col)
            for (int j = 0; j < 8; j++) {
                float t = A[col][j]; A[col][j] = A[piv][j]; A[piv][j] = t;
            }
        float inv = 1.f / A[col][col];
        for (int j = 0; j < 8; j++) A[col][j] *= inv;
        for (int r = 0; r < 4; r++) {
            if (r == col) continue;
            float f = A[r][col];
            for (int j = 0; j < 8; j++) A[r][j] -= f * A[col][j];
        }
    }
    #pragma unroll
    for (int i = 0; i < 4; i++)
        #pragma unroll
        for (int j = 0; j < 4; j++) {
            float s = 0.f;
            #pragma unroll
            for (int k = 0; k < 4; k++)
                s += cur_ext[(size_t)b * 16 + i * 4 + k] * A[k][4 + j];
            g_xf[b * 16 + i * 4 + j] = s;
        }
}

// ---------------------------------------------------------------------------
using FragA = wmma::fragment<wmma::matrix_a, 16, 16, 16, __half, wmma::col_major>;
using FragB = wmma::fragment<wmma::matrix_b, 16, 16, 16, __half, wmma::row_major>;
using FragC = wmma::fragment<wmma::accumulator, 16, 16, 16, float>;

__global__ void __launch_bounds__(kTHREADS, 1)
fused_kernel(const float* __restrict__ img,
             const float* __restrict__ mem,
             const float* __restrict__ Ws,
             const float* __restrict__ bs,
             float* __restrict__ out) {
    extern __shared__ float sm[];
    __half* W0h = (__half*)(sm + W0F);   // [k][out] ld 136
    __half* W1h = (__half*)(sm + W1F);
    __half* W2h = (__half*)(sm + W2F);   // [k][out2] ld 72, 144 rows (128=bias)
    __half* xsh = (__half*)(sm + XSF);   // [k][px]  ld 136, 144 rows (128=ones)
    float*  ysf = sm + YSF;              // [out][px] ld 132
    float*  sb  = sm + SBF;
    float*  sxf = sm + XFF;

    const int tid = threadIdx.x;
    const int wid = tid >> 5;

    // ---- one-time staging: weights (transposed [k][out], fp16) ----
    for (int i = tid; i < 128 * 128; i += kTHREADS) {
        int o = i >> 7, k = i & 127;                  // coalesced over k
        W0h[k * kLDW + o] = __float2half_rn(Ws[o * 128 + k]);
        W1h[k * kLDW + o] = __float2half_rn(Ws[16384 + o * 128 + k]);
    }
    for (int i = tid; i < 64 * 128; i += kTHREADS) {
        int o = i >> 7, k = i & 127;                  // out ch 64+o of layer 2
        W2h[k * kLDW2 + o] = __float2half_rn(Ws[2 * 16384 + (64 + o) * 128 + k]);
    }
    // W2 ext rows 128..143 (row 128 = layer-2 bias for out ch 64..127)
    for (int i = tid; i < 16 * kLDW2; i += kTHREADS) {
        int r = i / kLDW2, c = i % kLDW2;
        W2h[(128 + r) * kLDW2 + c] =
            (r == 0 && c < 64) ? __float2half_rn(bs[256 + 64 + c])
                               : __float2half_rn(0.f);
    }
    // xs ext rows 128..143 (row 128 = ones)
    for (int i = tid; i < 16 * kLDX; i += kTHREADS) {
        int r = i / kLDX, c = i % kLDX;
        xsh[(128 + r) * kLDX + c] = __float2half_rn(r == 0 ? 1.f : 0.f);
    }
    for (int i = tid; i < 256; i += kTHREADS) sb[i] = bs[i];
    __syncthreads();

    // warp tiling: 16 warps = 4 px-groups (32 px) x 4 out-groups
    const int pxg  = wid & 3;
    const int outg = wid >> 2;
    const int px0  = pxg * 32;

    for (int t = blockIdx.x; t < kNTiles; t += gridDim.x) {
        const int b  = t / kTilesPerB;
        const int p0 = (t - b * kTilesPerB) * kTP;

        if (tid < 16) sxf[tid] = g_xf[b * 16 + tid];
        const int useb = g_use[b];
        const int m    = g_midx[b];
        __syncthreads();   // prev tile L2 done with xs; sxf visible

        // ---- stage x tile rows 0..127 (fp16) ----
        #pragma unroll
        for (int n = 0; n < 4; n++) {                 // img -> rows 64..127
            int i  = tid + n * kTHREADS;
            int ch = i >> 5, q4 = (i & 31) * 4;
            const float* p = img + (size_t)(b * 64 + ch) * kHW + p0 + q4;
            float4 v = *(const float4*)p;
            st_half4(xsh + (64 + ch) * kLDX + q4, v.x, v.y, v.z, v.w);
        }
        if (useb) {
            #pragma unroll
            for (int n = 0; n < 2; n++) {             // mem -> rows 32..63
                int i  = tid + n * kTHREADS;
                int ch = i >> 5, q4 = (i & 31) * 4;
                const float* p = mem + (size_t)(m * 64 + 32 + ch) * kHW + p0 + q4;
                float4 v = *(const float4*)p;
                st_half4(xsh + (32 + ch) * kLDX + q4, v.x, v.y, v.z, v.w);
            }
            if (tid < 256) {                          // FTL -> rows 0..31
                int g = tid >> 5, q4 = (tid & 31) * 4;
                const float* mp = mem + (size_t)(m * 64 + 4 * g) * kHW + p0 + q4;
                float4 v0 = *(const float4*)(mp);
                float4 v1 = *(const float4*)(mp + kHW);
                float4 v2 = *(const float4*)(mp + 2 * kHW);
                float4 v3 = *(const float4*)(mp + 3 * kHW);
                #pragma unroll
                for (int r = 0; r < 4; r++) {
                    float a0 = sxf[r*4+0], a1 = sxf[r*4+1];
                    float a2 = sxf[r*4+2], a3 = sxf[r*4+3];
                    st_half4(xsh + (4 * g + r) * kLDX + q4,
                             a0*v0.x + a1*v1.x + a2*v2.x + a3*v3.x,
                             a0*v0.y + a1*v1.y + a2*v2.y + a3*v3.y,
                             a0*v0.z + a1*v1.z + a2*v2.z + a3*v3.z,
                             a0*v0.w + a1*v1.w + a2*v2.w + a3*v3.w);
                }
            }
        } else {
            // zeros -> rows 0..63 (FIXED: exact coverage, 2048 uint2 stores)
            #pragma unroll
            for (int n = 0; n < 4; n++) {
                int i  = tid + n * kTHREADS;          // [0, 2048)
                int ch = i >> 5;                      // row 0..63
                int q  = (i & 31) * 4;                // half offset 0..124
                *(uint2*)(xsh + ch * kLDX + q) = make_uint2(0u, 0u);
            }
        }
        __syncthreads();

        // ---- layers 0,1: Y[px][out] = Xt @ Wt (K=128) -> ys -> relu -> xs ----
        #pragma unroll 1
        for (int l = 0; l < 2; l++) {
            const __half* W = l ? W1h : W0h;
            const int out0 = outg * 32;

            FragC c[2][2];
            #pragma unroll
            for (int i = 0; i < 2; i++)
                #pragma unroll
                for (int j = 0; j < 2; j++)
                    wmma::fill_fragment(c[i][j], 0.f);

            #pragma unroll 4
            for (int k0 = 0; k0 < 128; k0 += 16) {
                FragA a[2];
                FragB bf[2];
                wmma::load_matrix_sync(a[0], xsh + px0      + k0 * kLDX, kLDX);
                wmma::load_matrix_sync(a[1], xsh + px0 + 16 + k0 * kLDX, kLDX);
                wmma::load_matrix_sync(bf[0], W + k0 * kLDW + out0,      kLDW);
                wmma::load_matrix_sync(bf[1], W + k0 * kLDW + out0 + 16, kLDW);
                #pragma unroll
                for (int i = 0; i < 2; i++)
                    #pragma unroll
                    for (int j = 0; j < 2; j++)
                        wmma::mma_sync(c[i][j], a[i], bf[j], c[i][j]);
            }
            // ys is a distinct buffer: no hazard with xs reads -> store now
            #pragma unroll
            for (int i = 0; i < 2; i++)
                #pragma unroll
                for (int j = 0; j < 2; j++)
                    wmma::store_matrix_sync(
                        ysf + (out0 + 16 * j) * kLDY + px0 + 16 * i,
                        c[i][j], kLDY, wmma::mem_col_major);
            __syncthreads();

            // bias + relu + fp16 convert: ys -> xs rows 0..127
            #pragma unroll
            for (int n = 0; n < 8; n++) {
                int i = tid + n * kTHREADS;
                int o = i >> 5, q4 = (i & 31) * 4;
                float bias = sb[l * 128 + o];
                float4 v = *(const float4*)(ysf + o * kLDY + q4);
                st_half4(xsh + o * kLDX + q4,
                         fmaxf(v.x + bias, 0.f), fmaxf(v.y + bias, 0.f),
                         fmaxf(v.z + bias, 0.f), fmaxf(v.w + bias, 0.f));
            }
            __syncthreads();
        }

        // ---- layer 2: K=144 (row 128 = ones x bias), out2=64, to gmem ----
        {
            const int out0 = outg * 16;
            FragC c2[2];
            wmma::fill_fragment(c2[0], 0.f);
            wmma::fill_fragment(c2[1], 0.f);

            #pragma unroll 3
            for (int k0 = 0; k0 < 144; k0 += 16) {
                FragA a[2];
                FragB bf;
                wmma::load_matrix_sync(a[0], xsh + px0      + k0 * kLDX, kLDX);
                wmma::load_matrix_sync(a[1], xsh + px0 + 16 + k0 * kLDX, kLDX);
                wmma::load_matrix_sync(bf, W2h + k0 * kLDW2 + out0, kLDW2);
                wmma::mma_sync(c2[0], a[0], bf, c2[0]);
                wmma::mma_sync(c2[1], a[1], bf, c2[1]);
            }
            float* op = out + (size_t)(b * 64 + out0) * kHW + p0 + px0;
            wmma::store_matrix_sync(op,      c2[0], kHW, wmma::mem_col_major);
            wmma::store_matrix_sync(op + 16, c2[1], kHW, wmma::mem_col_major);
        }
        // loop-head __syncthreads guards xs restaging
    }
}

// ---------------------------------------------------------------------------
extern "C" void kernel_launch(void* const* d_in, const int* in_sizes, int n_in,
                              void* d_out, int out_size) {
    const float* img      = (const float*)d_in[0];
    const float* mem      = (const float*)d_in[1];
    const float* prev_ext = (const float*)d_in[2];
    const float* cur_ext  = (const float*)d_in[3];
    const int*   midx     = (const int*)d_in[4];
    const unsigned char* use_raw = (const unsigned char*)d_in[5];
    const float* Ws       = (const float*)d_in[6];
    const float* bs       = (const float*)d_in[7];
    float*       out      = (float*)d_out;

    static int nsm = 0;
    if (nsm == 0) {
        int dev = 0;
        cudaGetDevice(&dev);
        cudaDeviceGetAttribute(&nsm, cudaDevAttrMultiProcessorCount, dev);
        if (nsm <= 0) nsm = 148;
        cudaFuncSetAttribute(fused_kernel,
                             cudaFuncAttributeMaxDynamicSharedMemorySize,
                             (int)SMEM_BYTES);
    }

    prep_kernel<<<1, 32>>>(prev_ext, cur_ext, midx, use_raw);
    fused_kernel<<<nsm, kTHREADS, SMEM_BYTES>>>(img, mem, Ws, bs, out);
}

// round 7
// speedup vs baseline: 7.2605x; 1.2405x over previous
#include <cuda_runtime.h>
#include <cuda_fp16.h>
#include <cstdint>
#include <math.h>

// ---------------------------------------------------------------------------
// SimpleConvRNN fused kernel for GB300 (sm_103a) — round 7: raw mma.sync fp16
// m16n8k16 + ldmatrix, in-register epilogue (bias+relu+cvt), double-buffered
// activation tiles (4 syncs/tile), persistent CTAs, 768 threads.
// ---------------------------------------------------------------------------

namespace {
constexpr int kB   = 32;
constexpr int kHW  = 6144;
constexpr int kTP  = 192;                   // pixels per tile
constexpr int kTilesPerB = 32;
constexpr int kNTiles = kB * kTilesPerB;    // 1024
constexpr int kTHREADS = 768;

constexpr int kLDW  = 136;                  // W0/W1 pitch (halves), 272B rows
constexpr int kLDW2 = 72;                   // W2 pitch (halves), 144B rows
constexpr int kLDX  = 200;                  // xs pitch (halves), 400B rows

// byte offsets in dynamic smem (all 16B aligned)
constexpr int W0B = 0;                      // 128 x 136 halves
constexpr int W1B = W0B + 128 * kLDW * 2;   // 34816
constexpr int W2B = W1B + 128 * kLDW * 2;   // 69632 (64 out-ch x 128 k)
constexpr int X0B = W2B + 128 * kLDW2 * 2;  // 88064
constexpr int X1B = X0B + 128 * kLDX * 2;   // 139264
constexpr int XFB = X1B + 128 * kLDX * 2;   // 190464 (16 floats xf)
constexpr size_t SMEM_BYTES = XFB + 64;     // 190528 B
}

__device__ __forceinline__ uint32_t smem_u32(const void* p) {
    uint32_t a;
    asm("{ .reg .u64 t; cvta.to.shared.u64 t, %1; cvt.u32.u64 %0, t; }"
        : "=r"(a) : "l"(p));
    return a;
}
__device__ __forceinline__ void ldsm4t(uint32_t r[4], uint32_t addr) {
    asm volatile("ldmatrix.sync.aligned.m8n8.x4.trans.shared.b16 "
                 "{%0,%1,%2,%3}, [%4];"
                 : "=r"(r[0]), "=r"(r[1]), "=r"(r[2]), "=r"(r[3]) : "r"(addr));
}
__device__ __forceinline__ void mma16816(float c[4], const uint32_t a[4],
                                         const uint32_t b0, const uint32_t b1) {
    asm volatile(
        "mma.sync.aligned.m16n8k16.row.col.f32.f16.f16.f32 "
        "{%0,%1,%2,%3}, {%4,%5,%6,%7}, {%8,%9}, {%0,%1,%2,%3};"
        : "+f"(c[0]), "+f"(c[1]), "+f"(c[2]), "+f"(c[3])
        : "r"(a[0]), "r"(a[1]), "r"(a[2]), "r"(a[3]), "r"(b0), "r"(b1));
}
__device__ __forceinline__ uint32_t h2pack(float a, float b) {
    __half2 h = __floats2half2_rn(a, b);
    return *(uint32_t*)&h;
}
__device__ __forceinline__ void st_half4(__half* p, float a, float b,
                                         float c, float d) {
    uint2 v;
    v.x = h2pack(a, b);
    v.y = h2pack(c, d);
    *(uint2*)p = v;
}

__device__ float g_xf[kB * 16];
__device__ int   g_use[kB];
__device__ int   g_midx[kB];

// ---------------------------------------------------------------------------
__global__ void prep_kernel(const float* __restrict__ prev_ext,
                            const float* __restrict__ cur_ext,
                            const int*   __restrict__ memory_idx,
                            const unsigned char* __restrict__ use_raw) {
    int b = threadIdx.x;
    if (b >= kB) return;

    const unsigned int* w32 = (const unsigned int*)use_raw;
    bool int_layout = true, float_layout = true;
    #pragma unroll
    for (int i = 0; i < 8; i++) {
        unsigned int v = w32[i];
        if (v != 0u && v != 1u)          int_layout = false;
        if (v != 0u && v != 0x3f800000u) float_layout = false;
    }
    int use;
    if (int_layout || float_layout) use = (w32[b] != 0u) ? 1 : 0;
    else                            use = use_raw[b] ? 1 : 0;
    g_use[b] = use;
    int m = memory_idx[b];
    g_midx[b] = m;

    float A[4][8];
    #pragma unroll
    for (int r = 0; r < 4; r++)
        #pragma unroll
        for (int c = 0; c < 4; c++) {
            A[r][c]     = use ? prev_ext[(size_t)m * 16 + r * 4 + c]
                              : (r == c ? 1.f : 0.f);
            A[r][c + 4] = (r == c) ? 1.f : 0.f;
        }
    for (int col = 0; col < 4; col++) {
        int piv = col;
        float best = fabsf(A[col][col]);
        for (int r = col + 1; r < 4; r++) {
            float v = fabsf(A[r][col]);
            if (v > best) { best = v; piv = r; }
        }
        if (piv != col)
            for (int j = 0; j < 8; j++) {
                float t = A[col][j]; A[col][j] = A[piv][j]; A[piv][j] = t;
            }
        float inv = 1.f / A[col][col];
        for (int j = 0; j < 8; j++) A[col][j] *= inv;
        for (int r = 0; r < 4; r++) {
            if (r == col) continue;
            float f = A[r][col];
            for (int j = 0; j < 8; j++) A[r][j] -= f * A[col][j];
        }
    }
    #pragma unroll
    for (int i = 0; i < 4; i++)
        #pragma unroll
        for (int j = 0; j < 4; j++) {
            float s = 0.f;
            #pragma unroll
            for (int k = 0; k < 4; k++)
                s += cur_ext[(size_t)b * 16 + i * 4 + k] * A[k][4 + j];
            g_xf[b * 16 + i * 4 + j] = s;
        }
}

// ---------------------------------------------------------------------------
// One 128x(32out x 32px) layer slice: C = W(out,k) @ X(k,px), K=128.
// aW/aB are this lane's ldmatrix base addresses; epilogue bias+relu+fp16 ->
// xs write buffer (byte base xw, transposed [out][px]).
__device__ __forceinline__ void layer_gemm(
    uint32_t aW, uint32_t aB, const float bl[4],
    uint32_t xw, int out0, int px0, int r, int col2)
{
    float c[8][4];
    #pragma unroll
    for (int i = 0; i < 8; i++)
        #pragma unroll
        for (int j = 0; j < 4; j++) c[i][j] = 0.f;

    #pragma unroll
    for (int k = 0; k < 8; k++) {
        uint32_t a0[4], a1[4], b0[4], b1[4];
        ldsm4t(a0, aW);
        ldsm4t(a1, aW + 32);                 // out0+16 (16 halves)
        ldsm4t(b0, aB);
        ldsm4t(b1, aB + 32);                 // px0+16
        mma16816(c[0], a0, b0[0], b0[1]);
        mma16816(c[1], a0, b0[2], b0[3]);
        mma16816(c[2], a0, b1[0], b1[1]);
        mma16816(c[3], a0, b1[2], b1[3]);
        mma16816(c[4], a1, b0[0], b0[1]);
        mma16816(c[5], a1, b0[2], b0[3]);
        mma16816(c[6], a1, b1[0], b1[1]);
        mma16816(c[7], a1, b1[2], b1[3]);
        aW += 16 * kLDW * 2;
        aB += 16 * kLDX * 2;
    }

    // epilogue: bias + relu + fp16, STS into xw[out][px]
    #pragma unroll
    for (int f = 0; f < 2; f++) {
        float bhi = bl[2 * f], blo = bl[2 * f + 1];
        #pragma unroll
        for (int p = 0; p < 4; p++) {
            const float* cc = c[f * 4 + p];
            uint32_t h01 = h2pack(fmaxf(cc[0] + bhi, 0.f),
                                  fmaxf(cc[1] + bhi, 0.f));
            uint32_t h23 = h2pack(fmaxf(cc[2] + blo, 0.f),
                                  fmaxf(cc[3] + blo, 0.f));
            int row = out0 + 16 * f + r;
            int col = px0 + 8 * p + col2;
            uint32_t addr = xw + (uint32_t)(row * kLDX + col) * 2;
            asm volatile("st.shared.b32 [%0], %1;" :: "r"(addr), "r"(h01));
            asm volatile("st.shared.b32 [%0], %1;"
                         :: "r"(addr + 8 * kLDX * 2), "r"(h23));
        }
    }
}

// ---------------------------------------------------------------------------
__global__ void __launch_bounds__(kTHREADS, 1)
fused_kernel(const float* __restrict__ img,
             const float* __restrict__ mem,
             const float* __restrict__ Ws,
             const float* __restrict__ bs,
             float* __restrict__ out) {
    extern __shared__ char smc[];
    const uint32_t sb = smem_u32(smc);
    __half* W0h = (__half*)(smc + W0B);
    __half* W1h = (__half*)(smc + W1B);
    __half* W2h = (__half*)(smc + W2B);
    __half* xs0 = (__half*)(smc + X0B);
    float*  sxf = (float*)(smc + XFB);

    const int tid  = threadIdx.x;
    const int wid  = tid >> 5;
    const int lane = tid & 31;
    const int r    = lane >> 2;
    const int col2 = (lane & 3) * 2;

    // ---- one-time weight staging (transposed [k][out], fp16) ----
    for (int i = tid; i < 128 * 128; i += kTHREADS) {
        int o = i >> 7, k = i & 127;
        W0h[k * kLDW + o] = __float2half_rn(Ws[o * 128 + k]);
        W1h[k * kLDW + o] = __float2half_rn(Ws[16384 + o * 128 + k]);
    }
    for (int i = tid; i < 64 * 128; i += kTHREADS) {
        int o = i >> 7, k = i & 127;            // layer-2 out ch 64+o
        W2h[k * kLDW2 + o] = __float2half_rn(Ws[2 * 16384 + (64 + o) * 128 + k]);
    }

    // ---- warp tiling + per-thread bias registers ----
    const int out0  = (wid & 3) * 32;          // L0/L1 out block
    const int px0   = (wid >> 2) * 32;         // px block (6 groups x 32)
    const int out20 = (wid & 3) * 16;          // L2 out block (0..63)
    float bL0[4], bL1[4], bL2[2];
    #pragma unroll
    for (int j = 0; j < 4; j++) {
        bL0[j] = bs[out0 + r + 8 * j];
        bL1[j] = bs[128 + out0 + r + 8 * j];
    }
    bL2[0] = bs[256 + 64 + out20 + r];
    bL2[1] = bs[256 + 64 + out20 + r + 8];

    // ---- lane-derived ldmatrix offsets ----
    const int lA_k = (lane & 7) + ((lane & 16) ? 8 : 0);
    const int lA_c = (lane & 8) ? 8 : 0;
    const int lB_k = (lane & 7) + ((lane & 8) ? 8 : 0);
    const int lB_c = (lane & 16) ? 8 : 0;

    const uint32_t aW0 = sb + W0B + (uint32_t)(lA_k * kLDW + out0 + lA_c) * 2;
    const uint32_t aW1 = sb + W1B + (uint32_t)(lA_k * kLDW + out0 + lA_c) * 2;
    const uint32_t aW2 = sb + W2B + (uint32_t)(lA_k * kLDW2 + out20 + lA_c) * 2;
    const uint32_t aB0 = sb + X0B + (uint32_t)(lB_k * kLDX + px0 + lB_c) * 2;
    const uint32_t aB1 = sb + X1B + (uint32_t)(lB_k * kLDX + px0 + lB_c) * 2;

    __syncthreads();

    for (int t = blockIdx.x; t < kNTiles; t += gridDim.x) {
        const int b  = t >> 5;                 // kTilesPerB = 32
        const int p0 = (t & 31) * kTP;

        if (tid < 16) sxf[tid] = g_xf[b * 16 + tid];
        const int useb = g_use[b];
        const int m    = g_midx[b];
        __syncthreads();   // S1: prior L2 done with xs0; sxf visible

        // ---- stage x tile into xs0 (fp16) ----
        #pragma unroll
        for (int n = 0; n < 4; n++) {              // img -> rows 64..127
            int i  = tid + n * kTHREADS;           // [0,3072)
            int ch = i / 48, j4 = (i % 48) * 4;
            const float* p = img + (size_t)(b * 64 + ch) * kHW + p0 + j4;
            float4 v = *(const float4*)p;
            st_half4(xs0 + (64 + ch) * kLDX + j4, v.x, v.y, v.z, v.w);
        }
        if (useb) {
            #pragma unroll
            for (int n = 0; n < 2; n++) {          // mem -> rows 32..63
                int i  = tid + n * kTHREADS;       // [0,1536)
                int ch = i / 48, j4 = (i % 48) * 4;
                const float* p = mem + (size_t)(m * 64 + 32 + ch) * kHW + p0 + j4;
                float4 v = *(const float4*)p;
                st_half4(xs0 + (32 + ch) * kLDX + j4, v.x, v.y, v.z, v.w);
            }
            if (tid < 384) {                       // FTL -> rows 0..31
                int g = tid / 48, j4 = (tid % 48) * 4;
                const float* mp = mem + (size_t)(m * 64 + 4 * g) * kHW + p0 + j4;
                float4 v0 = *(const float4*)(mp);
                float4 v1 = *(const float4*)(mp + kHW);
                float4 v2 = *(const float4*)(mp + 2 * kHW);
                float4 v3 = *(const float4*)(mp + 3 * kHW);
                #pragma unroll
                for (int rr = 0; rr < 4; rr++) {
                    float a0 = sxf[rr*4+0], a1 = sxf[rr*4+1];
                    float a2 = sxf[rr*4+2], a3 = sxf[rr*4+3];
                    st_half4(xs0 + (4 * g + rr) * kLDX + j4,
                             a0*v0.x + a1*v1.x + a2*v2.x + a3*v3.x,
                             a0*v0.y + a1*v1.y + a2*v2.y + a3*v3.y,
                             a0*v0.z + a1*v1.z + a2*v2.z + a3*v3.z,
                             a0*v0.w + a1*v1.w + a2*v2.w + a3*v3.w);
                }
            }
        } else {
            #pragma unroll
            for (int n = 0; n < 2; n++) {          // zeros -> rows 0..63
                int i   = tid + n * kTHREADS;      // [0,1536)
                int row = i / 24, c8 = (i % 24) * 8;
                *(uint4*)(smc + X0B + (row * kLDX + c8) * 2) =
                    make_uint4(0u, 0u, 0u, 0u);
            }
        }
        __syncthreads();   // S2

        // ---- L0: read xs0, write xs1 ----
        layer_gemm(aW0, aB0, bL0, sb + X1B, out0, px0, r, col2);
        __syncthreads();   // S3

        // ---- L1: read xs1, write xs0 ----
        layer_gemm(aW1, aB1, bL1, sb + X0B, out0, px0, r, col2);
        __syncthreads();   // S4

        // ---- L2: read xs0, C[16out x 32px] per warp, STG float2 ----
        {
            float c[4][4];
            #pragma unroll
            for (int i = 0; i < 4; i++)
                #pragma unroll
                for (int j = 0; j < 4; j++) c[i][j] = 0.f;

            uint32_t aA = aW2;
            uint32_t aB = aB0;
            #pragma unroll
            for (int k = 0; k < 8; k++) {
                uint32_t a0[4], b0[4], b1[4];
                ldsm4t(a0, aA);
                ldsm4t(b0, aB);
                ldsm4t(b1, aB + 32);
                mma16816(c[0], a0, b0[0], b0[1]);
                mma16816(c[1], a0, b0[2], b0[3]);
                mma16816(c[2], a0, b1[0], b1[1]);
                mma16816(c[3], a0, b1[2], b1[3]);
                aA += 16 * kLDW2 * 2;
                aB += 16 * kLDX * 2;
            }
            float* obase = out + (size_t)(b * 64 + out20 + r) * kHW + p0 + px0 + col2;
            #pragma unroll
            for (int p = 0; p < 4; p++) {
                float2 v01 = make_float2(c[p][0] + bL2[0], c[p][1] + bL2[0]);
                float2 v23 = make_float2(c[p][2] + bL2[1], c[p][3] + bL2[1]);
                *(float2*)(obase + 8 * p)                     = v01;
                *(float2*)(obase + 8 * p + (size_t)8 * kHW)   = v23;
            }
        }
        // loop-head S1 guards xs0 restaging
    }
}

// ---------------------------------------------------------------------------
extern "C" void kernel_launch(void* const* d_in, const int* in_sizes, int n_in,
                              void* d_out, int out_size) {
    const float* img      = (const float*)d_in[0];
    const float* mem      = (const float*)d_in[1];
    const float* prev_ext = (const float*)d_in[2];
    const float* cur_ext  = (const float*)d_in[3];
    const int*   midx     = (const int*)d_in[4];
    const unsigned char* use_raw = (const unsigned char*)d_in[5];
    const float* Ws       = (const float*)d_in[6];
    const float* bs       = (const float*)d_in[7];
    float*       out      = (float*)d_out;

    static int nsm = 0;
    if (nsm == 0) {
        int dev = 0;
        cudaGetDevice(&dev);
        cudaDeviceGetAttribute(&nsm, cudaDevAttrMultiProcessorCount, dev);
        if (nsm <= 0) nsm = 148;
        cudaFuncSetAttribute(fused_kernel,
                             cudaFuncAttributeMaxDynamicSharedMemorySize,
                             (int)SMEM_BYTES);
    }

    prep_kernel<<<1, 32>>>(prev_ext, cur_ext, midx, use_raw);
    fused_kernel<<<nsm, kTHREADS, SMEM_BYTES>>>(img, mem, Ws, bs, out);
}